// round 12
// baseline (speedup 1.0000x reference)
#include <cuda_runtime.h>
#include <math.h>

#define T_LEN 32
#define KP    2048
#define CPB   16                       // columns per CTA
#define GPC   16                       // threads per column
#define BLOCK 256
#define GRID  128                      // 1 CTA/SM, all co-resident

// sp = sqrt(1/32); 0.5/sp^2 = 16 exactly
#define LOG_SP     (-1.7328679513998633f)
#define HALF_L2PI  (0.9189385332046727f)
#define LOG_K      (7.6246189861593985f)
#define C2EXP      (-23.083120654223414f)   // -16 * log2(e)
#define L2E        (1.4426950408889634f)
#define F_INF      (__int_as_float(0x7f800000))

__device__ float g_zs[T_LEN * KP];
__device__ float g_A [T_LEN * KP];
__device__ float g_rb[T_LEN][KP];
__device__ float g_pmax[T_LEN][GRID];
__device__ int   g_flag[GRID];
__device__ int   g_epoch;

__device__ __forceinline__ float ex2(float t) {
    float r; asm("ex2.approx.ftz.f32 %0,%1;" : "=f"(r) : "f"(t)); return r;
}

__global__ void init_kernel() {
    int i = threadIdx.x;
    if (i < GRID) *(volatile int*)&g_flag[i] = 0;
    if (i == 0)   *(volatile int*)&g_epoch  = 0;
}

__global__ void __launch_bounds__(BLOCK) persist_kernel(const float* __restrict__ means,
                                                        const float* __restrict__ log_stds,
                                                        const float* __restrict__ eps,
                                                        float* __restrict__ out) {
    __shared__ __align__(16) float az[KP];   // -z_{t-1}
    __shared__ __align__(16) float w [KP];   // C2*z^2 then += (r - x)*log2e
    __shared__ float xsh;
    __shared__ float cred[CPB];
    __shared__ float red[8];

    const int tid  = threadIdx.x;
    const int wid  = tid >> 5;
    const int lane = tid & 31;
    const int c    = tid >> 4;
    const int g    = tid & (GPC - 1);
    const int cta  = blockIdx.x;
    const int k    = cta * CPB + c;

    // ================= setup phase: 512 elements per CTA =================
    float r0max = -F_INF;
    #pragma unroll
    for (int s = 0; s < 2; s++) {
        int idx = cta * 512 + tid + s * 256;
        int t  = idx >> 11;
        int kk = idx & (KP - 1);
        float mu = means[t];
        float sg = expf(log_stds[t]);
        float z  = fmaf(sg, eps[idx], mu);
        float zq = (z - mu) / sg;
        float lq = fmaf(-0.5f * zq, zq, -logf(sg)) - HALF_L2PI;
        __stcg(&g_zs[idx], z);
        __stcg(&g_A[idx], -LOG_SP - HALF_L2PI - lq);
        if (idx < KP) {
            float zz = z * 5.656854249492380f;   // z / sp
            float r0 = fmaf(-0.5f * zz, zz, -LOG_SP) - HALF_L2PI - lq;
            __stcg(&g_rb[0][kk], r0);
            r0max = fmaxf(r0max, r0);
        }
    }
    #pragma unroll
    for (int s = 16; s; s >>= 1)
        r0max = fmaxf(r0max, __shfl_xor_sync(0xffffffffu, r0max, s));
    if (lane == 0) red[wid] = r0max;
    __syncthreads();
    if (tid < 8) {
        float v = red[tid];
        #pragma unroll
        for (int s = 4; s; s >>= 1)
            v = fmaxf(v, __shfl_xor_sync(0xffu, v, s, 8));
        if (tid == 0 && cta < 4) __stcg(&g_pmax[0][cta], v);
    }
    __threadfence();
    __syncthreads();
    if (tid == 0) *(volatile int*)&g_flag[cta] = 1;   // r_0 ready

    // prefetch for step 1
    float zkr = __ldcg(&g_zs[1 * KP + k]);
    float akr = __ldcg(&g_A [1 * KP + k]);
    {
        const float4* z4 = reinterpret_cast<const float4*>(g_zs + 0 * KP);
        float4* az4 = reinterpret_cast<float4*>(az);
        float4* w4  = reinterpret_cast<float4*>(w);
        #pragma unroll
        for (int s = 0; s < 2; s++) {
            int f = tid + s * 256;
            float4 v = __ldcg(&z4[f]);
            az4[f] = make_float4(-v.x, -v.y, -v.z, -v.w);
            w4[f]  = make_float4(C2EXP * v.x * v.x, C2EXP * v.y * v.y,
                                 C2EXP * v.z * v.z, C2EXP * v.w * v.w);
        }
    }

    // ================= 31 scan steps =================
    for (int t = 1; t < T_LEN; t++) {
        // ---- barrier: wait until r_{t-1} globally ready ----
        if (cta == 0) {
            if (wid == 0) {
                volatile int* fl = g_flag;
                bool ok;
                do {
                    int m0 = fl[lane], m1 = fl[lane + 32], m2 = fl[lane + 64], m3 = fl[lane + 96];
                    int mn = min(min(m0, m1), min(m2, m3));
                    ok = __all_sync(0xffffffffu, mn >= t);
                } while (!ok);
                __threadfence();
                if (lane == 0) *(volatile int*)&g_epoch = t;
            }
            __syncthreads();
        } else {
            if (tid == 0) { while (*(volatile int*)&g_epoch < t) {} }
            __syncthreads();
        }
        __threadfence();

        // ---- post-barrier: r loads + x reduce (warp0) in parallel ----
        const float4* r4 = reinterpret_cast<const float4*>(g_rb[t - 1]);
        float4 ra = __ldcg(&r4[tid]);
        float4 rb = __ldcg(&r4[tid + 256]);
        if (wid == 0) {
            const int cnt = (t == 1) ? 4 : GRID;
            float m = -F_INF;
            for (int i = lane; i < cnt; i += 32)
                m = fmaxf(m, __ldcg(&g_pmax[t - 1][i]));
            #pragma unroll
            for (int s = 16; s; s >>= 1)
                m = fmaxf(m, __shfl_xor_sync(0xffffffffu, m, s));
            if (lane == 0) xsh = m;
        }
        __syncthreads();
        const float x   = xsh;
        const float nxl = -x * L2E;

        // ---- fold: w += (r - x)*log2e ----
        {
            float4* w4 = reinterpret_cast<float4*>(w);
            float4 wa = w4[tid];
            wa.x += fmaf(ra.x, L2E, nxl);
            wa.y += fmaf(ra.y, L2E, nxl);
            wa.z += fmaf(ra.z, L2E, nxl);
            wa.w += fmaf(ra.w, L2E, nxl);
            w4[tid] = wa;
            float4 wb = w4[tid + 256];
            wb.x += fmaf(rb.x, L2E, nxl);
            wb.y += fmaf(rb.y, L2E, nxl);
            wb.z += fmaf(rb.z, L2E, nxl);
            wb.w += fmaf(rb.w, L2E, nxl);
            w4[tid + 256] = wb;
        }
        __syncthreads();

        // ---- mainloop: S = sum_j 2^(czk2 + p2k*(-z_j) + w_j) ----
        const float czk2 = C2EXP * zkr * zkr;
        const float p2k  = 2.0f * C2EXP * zkr;
        const float2* az2 = reinterpret_cast<const float2*>(az);
        const float2* w2  = reinterpret_cast<const float2*>(w);
        float S0 = 0.0f, S1 = 0.0f;
        #pragma unroll 8
        for (int i = 0; i < KP / (2 * GPC); i++) {
            int f = i * GPC + g;                   // half-warps mirror -> broadcast
            float2 a2 = az2[f];
            float2 v2 = w2[f];
            S0 += ex2(fmaf(p2k, a2.x, v2.x) + czk2);
            S1 += ex2(fmaf(p2k, a2.y, v2.y) + czk2);
        }
        float S = S0 + S1;
        #pragma unroll
        for (int s = GPC / 2; s; s >>= 1)
            S += __shfl_xor_sync(0xffffffffu, S, s, GPC);

        // ---- epilogue: write r_t, per-CTA max, flag ----
        if (g == 0) {
            float val = x + akr + logf(fmaxf(S, 1e-37f)) - LOG_K;
            __stcg(&g_rb[t][k], val);
            cred[c] = val;
        }
        __syncthreads();
        if (tid < CPB) {
            float v = cred[tid];
            #pragma unroll
            for (int s = CPB / 2; s; s >>= 1)
                v = fmaxf(v, __shfl_xor_sync(0x0000ffffu, v, s, CPB));
            if (tid == 0) __stcg(&g_pmax[t][cta], v);
        }
        __threadfence();
        __syncthreads();
        if (tid == 0) *(volatile int*)&g_flag[cta] = t + 1;

        // ---- prefetch next step (overlaps others' compute / our wait) ----
        if (t + 1 < T_LEN) {
            zkr = __ldcg(&g_zs[(t + 1) * KP + k]);
            akr = __ldcg(&g_A [(t + 1) * KP + k]);
            const float4* z4 = reinterpret_cast<const float4*>(g_zs + t * KP);
            float4* az4 = reinterpret_cast<float4*>(az);
            float4* w4  = reinterpret_cast<float4*>(w);
            #pragma unroll
            for (int s = 0; s < 2; s++) {
                int f = tid + s * 256;
                float4 v = __ldcg(&z4[f]);
                az4[f] = make_float4(-v.x, -v.y, -v.z, -v.w);
                w4[f]  = make_float4(C2EXP * v.x * v.x, C2EXP * v.y * v.y,
                                     C2EXP * v.z * v.z, C2EXP * v.w * v.w);
            }
        }
    }

    // ================= final factor: CTA 0 only =================
    if (cta != 0) return;
    if (wid == 0) {
        volatile int* fl = g_flag;
        bool ok;
        do {
            int m0 = fl[lane], m1 = fl[lane + 32], m2 = fl[lane + 64], m3 = fl[lane + 96];
            int mn = min(min(m0, m1), min(m2, m3));
            ok = __all_sync(0xffffffffu, mn >= T_LEN);
        } while (!ok);
    }
    __syncthreads();
    __threadfence();

    const float* __restrict__ zrow = g_zs + (T_LEN - 1) * KP;
    float lr = -F_INF, lL = -F_INF;
    #pragma unroll
    for (int i = 0; i < KP / BLOCK; i++) {
        int j = tid + i * BLOCK;
        float r  = __ldcg(&g_rb[T_LEN - 1][j]);
        float dd = 0.5f - __ldcg(&zrow[j]);
        float Lv = fmaf(-0.5f * dd, dd, -HALF_L2PI);
        az[j] = r;
        w[j]  = Lv;
        lr = fmaxf(lr, r);
        lL = fmaxf(lL, Lv);
    }
    #pragma unroll
    for (int s = 16; s; s >>= 1) {
        lr = fmaxf(lr, __shfl_xor_sync(0xffffffffu, lr, s));
        lL = fmaxf(lL, __shfl_xor_sync(0xffffffffu, lL, s));
    }
    if (lane == 0) { red[wid] = lr; cred[wid] = lL; }
    __syncthreads();
    float x = red[0], y = cred[0];
    #pragma unroll
    for (int ww = 1; ww < 8; ww++) {
        x = fmaxf(x, red[ww]);
        y = fmaxf(y, cred[ww]);
    }

    float S = 0.0f;
    #pragma unroll
    for (int i = 0; i < KP / BLOCK; i++) {
        int j = tid + i * BLOCK;
        S += ex2(((az[j] - x) + (w[j] - y)) * L2E);
    }
    #pragma unroll
    for (int s = 16; s; s >>= 1)
        S += __shfl_xor_sync(0xffffffffu, S, s);
    if (lane == 0) red[wid] = S;
    __syncthreads();
    if (tid == 0) {
        float tot = 0.0f;
        #pragma unroll
        for (int ww = 0; ww < 8; ww++) tot += red[ww];
        out[0] = x + y + logf(tot) - LOG_K;
    }
}

extern "C" void kernel_launch(void* const* d_in, const int* in_sizes, int n_in,
                              void* d_out, int out_size) {
    const float* means    = (const float*)d_in[0];
    const float* log_stds = (const float*)d_in[1];
    const float* eps      = (const float*)d_in[2];
    float* out = (float*)d_out;

    init_kernel<<<1, 128>>>();
    persist_kernel<<<GRID, BLOCK>>>(means, log_stds, eps, out);
}